// round 2
// baseline (speedup 1.0000x reference)
#include <cuda_runtime.h>
#include <math.h>

#define BB 32
#define HH 512
#define WW 512
#define CC 3
#define RR 9            // half-width
#define KK 19           // kernel size
#define TT 32           // output tile
#define HL (TT + 2*RR)  // 50: tile + halo
#define NTH 256
#define EPS 1e-4f

#define SMEM_FLOATS (CC*HL*HL + CC*HL*TT)   // 7500 + 4800 = 12300
#define SMEM_BYTES  (SMEM_FLOATS * 4)       // 49200 B

// scratch: centered = x0 - blur(x0)
__device__ float g_cent[(size_t)BB * HH * WW * CC];

__device__ __forceinline__ void gauss_w(float* w) {
    float s = 0.f;
#pragma unroll
    for (int i = 0; i < KK; i++) {
        float t = (float)(i - RR);
        w[i] = __expf(-0.5f * t * t);
        s += w[i];
    }
    float inv = 1.0f / s;
#pragma unroll
    for (int i = 0; i < KK; i++) w[i] *= inv;
}

#define SIN(c, r, xx) sin_[((c)*HL + (r))*HL + (xx)]
#define SHB(c, r, xx) sh_[((c)*HL + (r))*TT + (xx)]

// ---------------------------------------------------------------------------
// Kernel 1: centered = x0 - gaussian_blur(x0)   (separable, tiled)
// ---------------------------------------------------------------------------
__global__ __launch_bounds__(NTH)
void lcn_mean_kernel(const float* __restrict__ xg) {
    extern __shared__ float smem[];
    float* sin_ = smem;
    float* sh_  = smem + CC * HL * HL;

    const int tx0 = blockIdx.x * TT;
    const int ty0 = blockIdx.y * TT;
    const int b   = blockIdx.z;
    const int tid = threadIdx.x;

    float w[KK];
    gauss_w(w);

    const float* xb = xg + (size_t)b * HH * WW * CC;

    // ---- load halo region (zero padding outside image), planar per channel
    for (int idx = tid; idx < HL * HL * CC; idx += NTH) {
        int row = idx / (HL * CC);
        int rem = idx - row * (HL * CC);
        int xx  = rem / CC;
        int c   = rem - xx * CC;
        int gy = ty0 - RR + row;
        int gx = tx0 - RR + xx;
        float v = 0.f;
        if (gy >= 0 && gy < HH && gx >= 0 && gx < WW)
            v = xb[((size_t)gy * WW + gx) * CC + c];
        SIN(c, row, xx) = v;
    }
    __syncthreads();

    // ---- horizontal pass: 600 tasks (c, row, quad-of-8-outputs)
    for (int tk = tid; tk < CC * HL * 4; tk += NTH) {
        int c   = tk / (HL * 4);
        int rr  = tk - c * (HL * 4);
        int row = rr >> 2;
        int xb8 = (rr & 3) * 8;
        float acc[8];
#pragma unroll
        for (int o = 0; o < 8; o++) acc[o] = 0.f;
#pragma unroll
        for (int k = 0; k < 26; k++) {
            float v = SIN(c, row, xb8 + k);
#pragma unroll
            for (int o = 0; o < 8; o++) {
                int j = k - o;
                if (j >= 0 && j < KK) acc[o] = fmaf(w[j], v, acc[o]);
            }
        }
#pragma unroll
        for (int o = 0; o < 8; o++) SHB(c, row, xb8 + o) = acc[o];
    }
    __syncthreads();

    // ---- vertical pass: each thread owns 4 consecutive rows at column lx
    const int lx = tid & 31;
    const int yb = (tid >> 5) * 4;
    float cent[CC][4];
#pragma unroll
    for (int c = 0; c < CC; c++) {
        float acc[4] = {0.f, 0.f, 0.f, 0.f};
#pragma unroll
        for (int k = 0; k < 22; k++) {
            float v = SHB(c, yb + k, lx);
#pragma unroll
            for (int r = 0; r < 4; r++) {
                int j = k - r;
                if (j >= 0 && j < KK) acc[r] = fmaf(w[j], v, acc[r]);
            }
        }
#pragma unroll
        for (int r = 0; r < 4; r++)
            cent[c][r] = SIN(c, yb + r + RR, lx + RR) - acc[r];
    }

    float* cb = g_cent + (size_t)b * HH * WW * CC;
#pragma unroll
    for (int r = 0; r < 4; r++) {
        size_t o = ((size_t)(ty0 + yb + r) * WW + (tx0 + lx)) * CC;
        cb[o + 0] = cent[0][r];
        cb[o + 1] = cent[1][r];
        cb[o + 2] = cent[2][r];
    }
}

// ---------------------------------------------------------------------------
// Kernel 2: var = blur(centered^2); out = centered/(sqrt(var)+eps) * mask
// ---------------------------------------------------------------------------
__global__ __launch_bounds__(NTH)
void lcn_out_kernel(const float* __restrict__ mask, float* __restrict__ out) {
    extern __shared__ float smem[];
    float* sin_ = smem;
    float* sh_  = smem + CC * HL * HL;

    const int tx0 = blockIdx.x * TT;
    const int ty0 = blockIdx.y * TT;
    const int b   = blockIdx.z;
    const int tid = threadIdx.x;

    float w[KK];
    gauss_w(w);

    const float* cbi = g_cent + (size_t)b * HH * WW * CC;

    // ---- load centered halo region (zero padding), planar
    for (int idx = tid; idx < HL * HL * CC; idx += NTH) {
        int row = idx / (HL * CC);
        int rem = idx - row * (HL * CC);
        int xx  = rem / CC;
        int c   = rem - xx * CC;
        int gy = ty0 - RR + row;
        int gx = tx0 - RR + xx;
        float v = 0.f;
        if (gy >= 0 && gy < HH && gx >= 0 && gx < WW)
            v = cbi[((size_t)gy * WW + gx) * CC + c];
        SIN(c, row, xx) = v;
    }
    __syncthreads();

    // ---- cache the center (centered) values this thread outputs
    const int lx = tid & 31;
    const int yb = (tid >> 5) * 4;
    float cent[CC][4];
#pragma unroll
    for (int c = 0; c < CC; c++)
#pragma unroll
        for (int r = 0; r < 4; r++)
            cent[c][r] = SIN(c, yb + r + RR, lx + RR);
    __syncthreads();

    // ---- square smem in place
    for (int idx = tid; idx < CC * HL * HL; idx += NTH) {
        float v = sin_[idx];
        sin_[idx] = v * v;
    }
    __syncthreads();

    // ---- horizontal pass on squared values
    for (int tk = tid; tk < CC * HL * 4; tk += NTH) {
        int c   = tk / (HL * 4);
        int rr  = tk - c * (HL * 4);
        int row = rr >> 2;
        int xb8 = (rr & 3) * 8;
        float acc[8];
#pragma unroll
        for (int o = 0; o < 8; o++) acc[o] = 0.f;
#pragma unroll
        for (int k = 0; k < 26; k++) {
            float v = SIN(c, row, xb8 + k);
#pragma unroll
            for (int o = 0; o < 8; o++) {
                int j = k - o;
                if (j >= 0 && j < KK) acc[o] = fmaf(w[j], v, acc[o]);
            }
        }
#pragma unroll
        for (int o = 0; o < 8; o++) SHB(c, row, xb8 + o) = acc[o];
    }
    __syncthreads();

    // ---- vertical pass -> var -> output
    float res[CC][4];
#pragma unroll
    for (int c = 0; c < CC; c++) {
        float acc[4] = {0.f, 0.f, 0.f, 0.f};
#pragma unroll
        for (int k = 0; k < 22; k++) {
            float v = SHB(c, yb + k, lx);
#pragma unroll
            for (int r = 0; r < 4; r++) {
                int j = k - r;
                if (j >= 0 && j < KK) acc[r] = fmaf(w[j], v, acc[r]);
            }
        }
#pragma unroll
        for (int r = 0; r < 4; r++) {
            float stdv = sqrtf(acc[r]) + EPS;
            res[c][r] = cent[c][r] / stdv;
        }
    }

#pragma unroll
    for (int r = 0; r < 4; r++) {
        int gy = ty0 + yb + r;
        int gx = tx0 + lx;
        float m = mask[(size_t)(b * HH + gy) * WW + gx];
        size_t o = ((size_t)(b * HH + gy) * WW + gx) * CC;
        out[o + 0] = res[0][r] * m;
        out[o + 1] = res[1][r] * m;
        out[o + 2] = res[2][r] * m;
    }
}

// ---------------------------------------------------------------------------
extern "C" void kernel_launch(void* const* d_in, const int* in_sizes, int n_in,
                              void* d_out, int out_size) {
    const float* x0   = (const float*)d_in[0];
    const float* mask = (const float*)d_in[1];
    float* out = (float*)d_out;

    cudaFuncSetAttribute(lcn_mean_kernel,
                         cudaFuncAttributeMaxDynamicSharedMemorySize, SMEM_BYTES);
    cudaFuncSetAttribute(lcn_out_kernel,
                         cudaFuncAttributeMaxDynamicSharedMemorySize, SMEM_BYTES);

    dim3 grid(WW / TT, HH / TT, BB);
    lcn_mean_kernel<<<grid, NTH, SMEM_BYTES>>>(x0);
    lcn_out_kernel<<<grid, NTH, SMEM_BYTES>>>(mask, out);
}